// round 15
// baseline (speedup 1.0000x reference)
#include <cuda_runtime.h>
#include <cuda_fp16.h>
#include <cstdint>

typedef unsigned long long u64;
typedef unsigned int u32;

#define Bc 64
#define Tc 512
#define T2c 514
#define Ec 256
#define Hc 256
#define Vc 5000
#define NCH 16          // chunks
#define CST 32          // steps per chunk

// scratch (allocation-free rule: __device__ globals)
__device__ float g_pre0[Bc * Tc * Hc];
__device__ float g_pre1[Bc * Tc * Hc];
__device__ __half g_ahi[Bc * Tc * Hc];
__device__ __half g_alo[Bc * Tc * Hc];
__device__ __half g_bhi[Bc * Tc * Hc];
__device__ __half g_blo[Bc * Tc * Hc];
__device__ __half g_whi[Vc * Hc];
__device__ __half g_wih0[Hc * Ec];
__device__ __half g_wih1[Hc * Hc];
__device__ int g_f0[Bc * NCH];
__device__ int g_f1[16 * NCH];
__device__ int g_f2[16 * NCH];

// ---------------- helpers ----------------
__device__ __forceinline__ u32 smem_u32(const void* p) {
    u32 a; asm("{ .reg .u64 t; cvta.to.shared.u64 t, %1; cvt.u32.u64 %0, t; }" : "=r"(a) : "l"(p));
    return a;
}
__device__ __forceinline__ u64 pk2(float x, float y) {
    u64 r; asm("mov.b64 %0,{%1,%2};" : "=l"(r) : "f"(x), "f"(y)); return r;
}
__device__ __forceinline__ u64 fma2(u64 a, u64 b, u64 c) {
    u64 d; asm("fma.rn.f32x2 %0,%1,%2,%3;" : "=l"(d) : "l"(a), "l"(b), "l"(c)); return d;
}
__device__ __forceinline__ float2 up2(u64 p) {
    float2 r; asm("mov.b64 {%0,%1},%2;" : "=f"(r.x), "=f"(r.y) : "l"(p)); return r;
}
__device__ __forceinline__ void ldsm_x4(u32* r, u32 addr) {
    asm volatile("ldmatrix.sync.aligned.m8n8.x4.shared.b16 {%0,%1,%2,%3}, [%4];"
                 : "=r"(r[0]), "=r"(r[1]), "=r"(r[2]), "=r"(r[3]) : "r"(addr));
}
__device__ __forceinline__ void mma_f16(float* d, const u32* a, const u32* b) {
    asm volatile(
        "mma.sync.aligned.m16n8k16.row.col.f32.f16.f16.f32 "
        "{%0,%1,%2,%3},{%4,%5,%6,%7},{%8,%9},{%0,%1,%2,%3};"
        : "+f"(d[0]), "+f"(d[1]), "+f"(d[2]), "+f"(d[3])
        : "r"(a[0]), "r"(a[1]), "r"(a[2]), "r"(a[3]), "r"(b[0]), "r"(b[1]));
}
__device__ __forceinline__ void cpa16(u32 dst, const void* src, u32 sz) {
    asm volatile("cp.async.cg.shared.global [%0], [%1], 16, %2;"
                 :: "r"(dst), "l"(src), "r"(sz) : "memory");
}
__device__ __forceinline__ void cp_commit() {
    asm volatile("cp.async.commit_group;" ::: "memory");
}
__device__ __forceinline__ float tanh_acc(float x) {
    float ax = fabsf(x);
    float e;
    asm("ex2.approx.f32 %0, %1;" : "=f"(e) : "f"(-2.885390082f * ax));
    float denom;
    asm("rcp.approx.f32 %0, %1;" : "=f"(denom) : "f"(1.0f + e));
    float t = (1.0f - e) * denom;
    return copysignf(t, x);
}

// ---------------- embedding gather -> fp16 hi/lo ----------------
__global__ void embed_kernel(const int* __restrict__ x, const float* __restrict__ tab,
                             __half* __restrict__ hi, __half* __restrict__ lo) {
    int bt = blockIdx.x;
    int b = bt >> 9, t = bt & 511;
    int tok = x[b * T2c + t];
    float4 v = reinterpret_cast<const float4*>(tab + (size_t)tok * Ec)[threadIdx.x];
    __half h0 = __float2half_rn(v.x), h1 = __float2half_rn(v.y);
    __half h2 = __float2half_rn(v.z), h3 = __float2half_rn(v.w);
    __half l0 = __float2half_rn(v.x - __half2float(h0));
    __half l1 = __float2half_rn(v.y - __half2float(h1));
    __half l2 = __float2half_rn(v.z - __half2float(h2));
    __half l3 = __float2half_rn(v.w - __half2float(h3));
    size_t o = (size_t)bt * Ec + threadIdx.x * 4;
    *reinterpret_cast<ushort4*>(hi + o) = make_ushort4(
        __half_as_ushort(h0), __half_as_ushort(h1), __half_as_ushort(h2), __half_as_ushort(h3));
    *reinterpret_cast<ushort4*>(lo + o) = make_ushort4(
        __half_as_ushort(l0), __half_as_ushort(l1), __half_as_ushort(l2), __half_as_ushort(l3));
}

// ---------------- fp32 weights -> plain fp16 ----------------
__global__ void convw_kernel(const float* __restrict__ src, __half* __restrict__ dst) {
    size_t i = ((size_t)blockIdx.x * 256 + threadIdx.x) * 4;
    float4 v = *reinterpret_cast<const float4*>(src + i);
    *reinterpret_cast<ushort4*>(dst + i) = make_ushort4(
        __half_as_ushort(__float2half_rn(v.x)), __half_as_ushort(__float2half_rn(v.y)),
        __half_as_ushort(__float2half_rn(v.z)), __half_as_ushort(__float2half_rn(v.w)));
}

__global__ void reset_flags() {
    int i = threadIdx.x;
#pragma unroll
    for (int j = 0; j < 4; j++) g_f0[i * 4 + j] = 0;
    g_f1[i] = 0;
    g_f2[i] = 0;
}

// ---------------- HMMA fp16 1-term GEMM, 128x128 tile (output projection) ----------------
#define TILE_B 10240
#define STAGE1_B (2 * TILE_B)            // A | B
#define GEMM1_SMEM (3 * STAGE1_B)        // 61440

__global__ void __launch_bounds__(256, 2) mma_gemm_1t(
    const __half* __restrict__ Ah, const __half* __restrict__ Bh,
    const float* __restrict__ bias, float* __restrict__ C, int Nact)
{
    extern __shared__ __align__(16) char smem[];
    const u32 sb = smem_u32(smem);
    const int tid = threadIdx.x;
    const int wid = tid >> 5, lane = tid & 31;
    const int m0 = blockIdx.y * 128, n0 = blockIdx.x * 128;
    const int wm = (wid >> 2) * 64, wn = (wid & 3) * 32;

    const int row0 = tid >> 2, seg0 = tid & 3;
    const int row1 = (tid + 256) >> 2, seg1 = (tid + 256) & 3;

    float acc[4][4][4];
#pragma unroll
    for (int i = 0; i < 4; i++)
#pragma unroll
        for (int j = 0; j < 4; j++)
#pragma unroll
            for (int q = 0; q < 4; q++) acc[i][j][q] = 0.f;

    auto load_chunk = [&](int k0, int stage) {
        const u32 base = sb + stage * STAGE1_B;
#pragma unroll
        for (int h = 0; h < 2; h++) {
            const int row = h ? row1 : row0;
            const int seg = h ? seg1 : seg0;
            const u32 dst = base + row * 80 + seg * 16;
            cpa16(dst, Ah + (size_t)(m0 + row) * 256 + k0 + seg * 8, 16);
            const int br = n0 + row;
            const u32 sz = (br < Nact) ? 16u : 0u;
            const int brc = (br < Nact) ? br : (Nact - 1);
            cpa16(dst + TILE_B, Bh + (size_t)brc * 256 + k0 + seg * 8, sz);
        }
        cp_commit();
    };

    const u32 arow = (wm + (lane & 15)) * 80 + (lane >> 4) * 16;
    const u32 brow = (wn + (lane & 7) + ((lane >> 4) & 1) * 8) * 80 + ((lane >> 3) & 1) * 16;

    load_chunk(0, 0);
    load_chunk(32, 1);

#pragma unroll 1
    for (int ic = 0; ic < 8; ic++) {
        if (ic < 7) asm volatile("cp.async.wait_group 1;" ::: "memory");
        else        asm volatile("cp.async.wait_group 0;" ::: "memory");
        __syncthreads();
        if (ic < 6) load_chunk((ic + 2) * 32, (ic + 2) % 3);

        const u32 base = sb + (ic % 3) * STAGE1_B;
        const u32 aHi = base, bHm = base + TILE_B;
#pragma unroll
        for (int kk = 0; kk < 2; kk++) {
            u32 af[4][4], bf[2][4];
#pragma unroll
            for (int jb = 0; jb < 2; jb++)
                ldsm_x4(bf[jb], bHm + brow + jb * 16 * 80 + kk * 32);
#pragma unroll
            for (int im = 0; im < 4; im++)
                ldsm_x4(af[im], aHi + arow + im * 16 * 80 + kk * 32);
#pragma unroll
            for (int im = 0; im < 4; im++)
#pragma unroll
                for (int jn = 0; jn < 4; jn++)
                    mma_f16(acc[im][jn], af[im], &bf[jn >> 1][(jn & 1) * 2]);
        }
    }

    const int rbase = m0 + wm + (lane >> 2);
    const int cbase = n0 + wn + (lane & 3) * 2;
#pragma unroll
    for (int im = 0; im < 4; im++) {
#pragma unroll
        for (int jn = 0; jn < 4; jn++) {
            int n = cbase + jn * 8;
            if (n < Nact) {
                float bx = bias[n], by = bias[n + 1];
                int r0 = rbase + im * 16;
                *reinterpret_cast<float2*>(C + (size_t)r0 * Nact + n) =
                    make_float2(acc[im][jn][0] + bx, acc[im][jn][1] + by);
                *reinterpret_cast<float2*>(C + (size_t)(r0 + 8) * Nact + n) =
                    make_float2(acc[im][jn][2] + bx, acc[im][jn][3] + by);
            }
        }
    }
}

// ---------------- fused wavefront pipeline: gemm0 | scan0 | gemm1 | scan1 ----------------
// grid = 144 CTAs, all resident:
//   roles [0,64):    scan0 batch b (polls f2, pre0 -> h0 into ahi/alo), sets f0[b][c]
//   roles [64,128):  scan1 batch b (polls f1, pre1 -> h1 into bhi/blo, lstate1)
//   roles [128,144): gemm CTA g (4 batches): produces pre0 chunk c+1 eagerly (embed @ wih0,
//                    sets f2[g][c+1]), then waits f0 and produces pre1 chunk c (h0 @ wih1,
//                    sets f1[g][c]).
#define FSC_W4 16
#define FUSED_SMEM (FSC_W4 * 256 * 16 + 2 * 256 * 4)

__global__ void __launch_bounds__(256, 1) fused_pipeline(
    float* __restrict__ pre0, float* __restrict__ pre1,
    const float* __restrict__ Whh, const float* __restrict__ bhh,
    const __half* __restrict__ wih0, const float* __restrict__ bih0,
    const __half* __restrict__ wih1, const float* __restrict__ bih1,
    __half* __restrict__ ahi, __half* __restrict__ alo,
    __half* __restrict__ bhi, __half* __restrict__ blo,
    float* __restrict__ hlast)
{
    extern __shared__ __align__(16) float sm[];
    const int role = blockIdx.x;
    const int tid = threadIdx.x;

    if (role < 128) {
        // ---------------- scan role ----------------
        const int layer = role >> 6;
        const int b = role & 63;
        const int r = tid;
        float4* w4 = reinterpret_cast<float4*>(sm);
        float* hbuf = sm + FSC_W4 * 256 * 4;
        const float* W = Whh + (size_t)layer * Hc * Hc;

#pragma unroll
        for (int k4 = 0; k4 < FSC_W4; k4++)
            w4[k4 * 256 + r] = *reinterpret_cast<const float4*>(&W[r * 256 + k4 * 4]);
        u64 wreg[96];
#pragma unroll
        for (int j = 0; j < 48; j++) {
            ulonglong2 v = *reinterpret_cast<const ulonglong2*>(&W[r * 256 + 64 + j * 4]);
            wreg[2 * j] = v.x; wreg[2 * j + 1] = v.y;
        }
        const float bias = bhh[layer * Hc + r];
        hbuf[r] = 0.f;
        __syncthreads();

        const float* preb = (layer ? pre1 : pre0) + (size_t)b * Tc * Hc;
        __half* ohi = (layer ? bhi : ahi) + (size_t)b * Tc * Hc;
        __half* olo = (layer ? blo : alo) + (size_t)b * Tc * Hc;
        const ulonglong2* w2s = reinterpret_cast<const ulonglong2*>(sm);

        float hn = 0.f;
#pragma unroll 1
        for (int c = 0; c < NCH; c++) {
            // wait for this chunk's pre to be ready
            if (tid == 0) {
                int* flag = layer ? &g_f1[(b >> 2) * NCH + c] : &g_f2[(b >> 2) * NCH + c];
                while (atomicAdd(flag, 0) == 0) __nanosleep(200);
            }
            __syncthreads();
            __threadfence();

            float pc = preb[(c * CST) * Hc + r];
#pragma unroll 1
            for (int tt = 0; tt < CST; tt++) {
                const int t = c * CST + tt;
                float pn = (tt < CST - 1) ? preb[(t + 1) * Hc + r] : 0.f;
                const ulonglong2* hc = reinterpret_cast<const ulonglong2*>(hbuf + (t & 1) * 256);
                u64 a0 = pk2(pc + bias, 0.f), a1 = 0ull, a2 = 0ull, a3 = 0ull;
#pragma unroll
                for (int k4 = 0; k4 < FSC_W4; k4++) {
                    ulonglong2 w = w2s[k4 * 256 + r];
                    ulonglong2 h = hc[k4];
                    a0 = fma2(w.x, h.x, a0);
                    a0 = fma2(w.y, h.y, a0);
                }
#pragma unroll
                for (int j = 0; j < 16; j++) {
                    ulonglong2 h = hc[FSC_W4 + j];
                    a1 = fma2(wreg[2 * j], h.x, a1);
                    a1 = fma2(wreg[2 * j + 1], h.y, a1);
                }
#pragma unroll
                for (int j = 16; j < 32; j++) {
                    ulonglong2 h = hc[FSC_W4 + j];
                    a2 = fma2(wreg[2 * j], h.x, a2);
                    a2 = fma2(wreg[2 * j + 1], h.y, a2);
                }
#pragma unroll
                for (int j = 32; j < 48; j++) {
                    ulonglong2 h = hc[FSC_W4 + j];
                    a3 = fma2(wreg[2 * j], h.x, a3);
                    a3 = fma2(wreg[2 * j + 1], h.y, a3);
                }
                float2 p0 = up2(a0), p1 = up2(a1), p2 = up2(a2), p3 = up2(a3);
                hn = tanh_acc(((p0.x + p0.y) + (p1.x + p1.y)) + ((p2.x + p2.y) + (p3.x + p3.y)));
                __half hh = __float2half_rn(hn);
                __half hl = __float2half_rn(hn - __half2float(hh));
                ohi[t * Hc + r] = hh;
                olo[t * Hc + r] = hl;
                hbuf[((t + 1) & 1) * 256 + r] = hn;
                __syncthreads();
                pc = pn;
            }
            if (!layer) {
                __threadfence();
                __syncthreads();
                if (tid == 0) atomicExch(&g_f0[b * NCH + c], 1);
            }
        }
        hlast[layer * Bc * Hc + b * Hc + r] = hn;
    } else {
        // ---------------- gemm role: pre0 + pre1 chunk producer ----------------
        const int g = role - 128;
        const u32 sb = smem_u32(sm);
        const int wid = tid >> 5, lane = tid & 31;
        const int wm = (wid >> 2) * 64, wn = (wid & 3) * 32;
        const int row0 = tid >> 2, seg0 = tid & 3;
        const int row1 = (tid + 256) >> 2, seg1 = (tid + 256) & 3;
        const u32 arow = (wm + (lane & 15)) * 80 + (lane >> 4) * 16;
        const u32 brow = (wn + (lane & 7) + ((lane >> 4) & 1) * 8) * 80 + ((lane >> 3) & 1) * 16;

        // 2-term GEMM over 128 rows (4 batches x CST steps of chunk cc):
        // dst[(b,t),n] = [Ahi+Alo](b,t,:) @ W^T + bias
        auto produce = [&](int cc, const __half* W, const float* biasv, float* dst) {
#pragma unroll 1
            for (int nt = 0; nt < 2; nt++) {
                float acc[4][4][4];
#pragma unroll
                for (int i = 0; i < 4; i++)
#pragma unroll
                    for (int j = 0; j < 4; j++)
#pragma unroll
                        for (int q = 0; q < 4; q++) acc[i][j][q] = 0.f;

#pragma unroll 1
                for (int kc = 0; kc < 8; kc++) {
#pragma unroll
                    for (int h = 0; h < 2; h++) {
                        const int row = h ? row1 : row0;
                        const int seg = h ? seg1 : seg0;
                        const int bb = 4 * g + (row >> 5);
                        const int t = cc * CST + (row & 31);
                        const size_t aoff = ((size_t)(bb * 512 + t)) * 256 + kc * 32 + seg * 8;
                        const u32 dsts = sb + row * 80 + seg * 16;
                        cpa16(dsts, ahi + aoff, 16);
                        cpa16(dsts + TILE_B, alo + aoff, 16);
                        const size_t boff = (size_t)(nt * 128 + row) * 256 + kc * 32 + seg * 8;
                        cpa16(dsts + 2 * TILE_B, W + boff, 16);
                    }
                    cp_commit();
                    asm volatile("cp.async.wait_group 0;" ::: "memory");
                    __syncthreads();

                    const u32 aHi = sb, aLo = sb + TILE_B, bHm = sb + 2 * TILE_B;
#pragma unroll
                    for (int kk = 0; kk < 2; kk++) {
                        u32 af[4][4], bf[2][4];
#pragma unroll
                        for (int jb = 0; jb < 2; jb++)
                            ldsm_x4(bf[jb], bHm + brow + jb * 16 * 80 + kk * 32);
#pragma unroll
                        for (int im = 0; im < 4; im++)
                            ldsm_x4(af[im], aHi + arow + im * 16 * 80 + kk * 32);
#pragma unroll
                        for (int im = 0; im < 4; im++)
#pragma unroll
                            for (int jn = 0; jn < 4; jn++)
                                mma_f16(acc[im][jn], af[im], &bf[jn >> 1][(jn & 1) * 2]);
#pragma unroll
                        for (int im = 0; im < 4; im++)
                            ldsm_x4(af[im], aLo + arow + im * 16 * 80 + kk * 32);
#pragma unroll
                        for (int im = 0; im < 4; im++)
#pragma unroll
                            for (int jn = 0; jn < 4; jn++)
                                mma_f16(acc[im][jn], af[im], &bf[jn >> 1][(jn & 1) * 2]);
                    }
                    __syncthreads();
                }
#pragma unroll
                for (int im = 0; im < 4; im++) {
#pragma unroll
                    for (int jn = 0; jn < 4; jn++) {
                        const int n = nt * 128 + wn + (lane & 3) * 2 + jn * 8;
                        const float bx = biasv[n], by = biasv[n + 1];
                        const int rl0 = wm + (lane >> 2) + im * 16;
                        const int b0 = 4 * g + (rl0 >> 5), t0 = cc * CST + (rl0 & 31);
                        *reinterpret_cast<float2*>(dst + ((size_t)(b0 * 512 + t0)) * 256 + n) =
                            make_float2(acc[im][jn][0] + bx, acc[im][jn][1] + by);
                        const int rl1 = rl0 + 8;
                        const int b1 = 4 * g + (rl1 >> 5), t1 = cc * CST + (rl1 & 31);
                        *reinterpret_cast<float2*>(dst + ((size_t)(b1 * 512 + t1)) * 256 + n) =
                            make_float2(acc[im][jn][2] + bx, acc[im][jn][3] + by);
                    }
                }
            }
        };

        // pre0 chunk 0 first (embed data ready at kernel start)
        produce(0, wih0, bih0, pre0);
        __threadfence();
        __syncthreads();
        if (tid == 0) atomicExch(&g_f2[g * NCH + 0], 1);

#pragma unroll 1
        for (int c = 0; c < NCH; c++) {
            if (c + 1 < NCH) {                       // eager pre0 chunk c+1
                produce(c + 1, wih0, bih0, pre0);
                __threadfence();
                __syncthreads();
                if (tid == 0) atomicExch(&g_f2[g * NCH + c + 1], 1);
            }
            if (tid == 0) {                          // wait for scan0 chunk c (4 batches)
#pragma unroll 1
                for (int i = 0; i < 4; i++)
                    while (atomicAdd(&g_f0[(4 * g + i) * NCH + c], 0) == 0) __nanosleep(100);
            }
            __syncthreads();
            __threadfence();
            produce(c, wih1, bih1, pre1);            // pre1 chunk c
            __threadfence();
            __syncthreads();
            if (tid == 0) atomicExch(&g_f1[g * NCH + c], 1);
        }
    }
}

__global__ void tail_kernel(const int* __restrict__ x, float* __restrict__ outSeq) {
    int i = threadIdx.x;
    outSeq[i] = (float)x[i * T2c + (T2c - 1)];
}

extern "C" void kernel_launch(void* const* d_in, const int* in_sizes, int n_in,
                              void* d_out, int out_size) {
    const int*   x    = (const int*)d_in[0];
    const float* tab  = (const float*)d_in[1];
    const float* Wih  = (const float*)d_in[2];
    const float* Whh  = (const float*)d_in[3];
    const float* bih  = (const float*)d_in[4];
    const float* bhh  = (const float*)d_in[5];
    const float* Wout = (const float*)d_in[6];
    const float* bout = (const float*)d_in[7];
    float* out = (float*)d_out;

    float *pre0, *pre1;
    __half *ahi, *alo, *bhi, *blo, *whi, *wih0, *wih1;
    cudaGetSymbolAddress((void**)&pre0, g_pre0);
    cudaGetSymbolAddress((void**)&pre1, g_pre1);
    cudaGetSymbolAddress((void**)&ahi, g_ahi);
    cudaGetSymbolAddress((void**)&alo, g_alo);
    cudaGetSymbolAddress((void**)&bhi, g_bhi);
    cudaGetSymbolAddress((void**)&blo, g_blo);
    cudaGetSymbolAddress((void**)&whi, g_whi);
    cudaGetSymbolAddress((void**)&wih0, g_wih0);
    cudaGetSymbolAddress((void**)&wih1, g_wih1);

    cudaFuncSetAttribute(mma_gemm_1t, cudaFuncAttributeMaxDynamicSharedMemorySize, GEMM1_SMEM);
    cudaFuncSetAttribute(fused_pipeline, cudaFuncAttributeMaxDynamicSharedMemorySize, FUSED_SMEM);

    const size_t LOGITS = (size_t)Bc * Tc * Vc;
    float* lstate = out + LOGITS;
    float* seq = out + LOGITS + 2 * Bc * Hc;

    // prologue: embed + weight conversions + flag reset (all tiny)
    embed_kernel<<<Bc * Tc, 64>>>(x, tab, ahi, alo);
    convw_kernel<<<(Hc * Ec) / 1024, 256>>>(Wih, wih0);
    convw_kernel<<<(Hc * Ec) / 1024, 256>>>(Wih + Hc * Ec, wih1);
    convw_kernel<<<(Vc * Hc) / 1024, 256>>>(Wout, whi);
    reset_flags<<<1, 256>>>();

    // fused wavefront: gemm0 | scan0 | gemm1 | scan1
    fused_pipeline<<<144, 256, FUSED_SMEM>>>(pre0, pre1, Whh, bhh,
                                             wih0, bih, wih1, bih + Hc,
                                             ahi, alo, bhi, blo, lstate);

    // output projection: 1-term fp16, 128x128, 2 CTA/SM
    mma_gemm_1t<<<dim3((Vc + 127) / 128, 256), dim3(256), GEMM1_SMEM>>>(bhi, whi, bout, out, Vc);

    tail_kernel<<<1, Bc>>>(x, seq);
}

// round 17
// speedup vs baseline: 1.2369x; 1.2369x over previous
#include <cuda_runtime.h>
#include <cuda_fp16.h>
#include <cstdint>

typedef unsigned long long u64;
typedef unsigned int u32;

#define Bc 64
#define Tc 512
#define T2c 514
#define Ec 256
#define Hc 256
#define Vc 5000
#define NCH 16          // chunks
#define CST 32          // steps per chunk

// scratch (allocation-free rule: __device__ globals)
__device__ float g_pre0[Bc * Tc * Hc];
__device__ float g_pre1[Bc * Tc * Hc];
__device__ __half g_ahi[Bc * Tc * Hc];
__device__ __half g_alo[Bc * Tc * Hc];
__device__ __half g_bhi[Bc * Tc * Hc];
__device__ __half g_blo[Bc * Tc * Hc];
__device__ __half g_whi[Vc * Hc];
__device__ __half g_wih0[Hc * Ec];
__device__ __half g_wih1[Hc * Hc];
__device__ int g_f0[Bc * NCH];
__device__ int g_f1[16 * NCH];

// ---------------- helpers ----------------
__device__ __forceinline__ u32 smem_u32(const void* p) {
    u32 a; asm("{ .reg .u64 t; cvta.to.shared.u64 t, %1; cvt.u32.u64 %0, t; }" : "=r"(a) : "l"(p));
    return a;
}
__device__ __forceinline__ u64 pk2(float x, float y) {
    u64 r; asm("mov.b64 %0,{%1,%2};" : "=l"(r) : "f"(x), "f"(y)); return r;
}
__device__ __forceinline__ u64 fma2(u64 a, u64 b, u64 c) {
    u64 d; asm("fma.rn.f32x2 %0,%1,%2,%3;" : "=l"(d) : "l"(a), "l"(b), "l"(c)); return d;
}
__device__ __forceinline__ float2 up2(u64 p) {
    float2 r; asm("mov.b64 {%0,%1},%2;" : "=f"(r.x), "=f"(r.y) : "l"(p)); return r;
}
__device__ __forceinline__ void ldsm_x4(u32* r, u32 addr) {
    asm volatile("ldmatrix.sync.aligned.m8n8.x4.shared.b16 {%0,%1,%2,%3}, [%4];"
                 : "=r"(r[0]), "=r"(r[1]), "=r"(r[2]), "=r"(r[3]) : "r"(addr));
}
__device__ __forceinline__ void mma_f16(float* d, const u32* a, const u32* b) {
    asm volatile(
        "mma.sync.aligned.m16n8k16.row.col.f32.f16.f16.f32 "
        "{%0,%1,%2,%3},{%4,%5,%6,%7},{%8,%9},{%0,%1,%2,%3};"
        : "+f"(d[0]), "+f"(d[1]), "+f"(d[2]), "+f"(d[3])
        : "r"(a[0]), "r"(a[1]), "r"(a[2]), "r"(a[3]), "r"(b[0]), "r"(b[1]));
}
__device__ __forceinline__ void cpa16(u32 dst, const void* src, u32 sz) {
    asm volatile("cp.async.cg.shared.global [%0], [%1], 16, %2;"
                 :: "r"(dst), "l"(src), "r"(sz) : "memory");
}
__device__ __forceinline__ void cp_commit() {
    asm volatile("cp.async.commit_group;" ::: "memory");
}
__device__ __forceinline__ float tanh_acc(float x) {
    float ax = fabsf(x);
    float e;
    asm("ex2.approx.f32 %0, %1;" : "=f"(e) : "f"(-2.885390082f * ax));
    float denom;
    asm("rcp.approx.f32 %0, %1;" : "=f"(denom) : "f"(1.0f + e));
    float t = (1.0f - e) * denom;
    return copysignf(t, x);
}

// ---------------- embedding gather -> fp16 hi/lo (256 thr, 4 rows/block) ----------------
__global__ void embed_kernel(const int* __restrict__ x, const float* __restrict__ tab,
                             __half* __restrict__ hi, __half* __restrict__ lo) {
    int idx = blockIdx.x * 4 + (threadIdx.x >> 6);     // (b,t) row
    int lane = threadIdx.x & 63;
    int b = idx >> 9, t = idx & 511;
    int tok = x[b * T2c + t];
    float4 v = reinterpret_cast<const float4*>(tab + (size_t)tok * Ec)[lane];
    __half h0 = __float2half_rn(v.x), h1 = __float2half_rn(v.y);
    __half h2 = __float2half_rn(v.z), h3 = __float2half_rn(v.w);
    __half l0 = __float2half_rn(v.x - __half2float(h0));
    __half l1 = __float2half_rn(v.y - __half2float(h1));
    __half l2 = __float2half_rn(v.z - __half2float(h2));
    __half l3 = __float2half_rn(v.w - __half2float(h3));
    size_t o = (size_t)idx * Ec + lane * 4;
    *reinterpret_cast<ushort4*>(hi + o) = make_ushort4(
        __half_as_ushort(h0), __half_as_ushort(h1), __half_as_ushort(h2), __half_as_ushort(h3));
    *reinterpret_cast<ushort4*>(lo + o) = make_ushort4(
        __half_as_ushort(l0), __half_as_ushort(l1), __half_as_ushort(l2), __half_as_ushort(l3));
}

// ---------------- one-shot prep: all weight conversions + flag reset ----------------
__device__ __forceinline__ void conv_blk(const float* __restrict__ src,
                                         __half* __restrict__ dst, int blk, int tid) {
    size_t i = ((size_t)blk * 256 + tid) * 4;
    float4 v = *reinterpret_cast<const float4*>(src + i);
    *reinterpret_cast<ushort4*>(dst + i) = make_ushort4(
        __half_as_ushort(__float2half_rn(v.x)), __half_as_ushort(__float2half_rn(v.y)),
        __half_as_ushort(__float2half_rn(v.z)), __half_as_ushort(__float2half_rn(v.w)));
}
#define PREP_WOUT 1250
#define PREP_BLOCKS (PREP_WOUT + 64 + 64 + 1)
__global__ void prep_kernel(const float* __restrict__ Wih, const float* __restrict__ Wout) {
    const int bid = blockIdx.x, tid = threadIdx.x;
    if (bid < PREP_WOUT) {
        conv_blk(Wout, g_whi, bid, tid);
    } else if (bid < PREP_WOUT + 64) {
        conv_blk(Wih, g_wih0, bid - PREP_WOUT, tid);
    } else if (bid < PREP_WOUT + 128) {
        conv_blk(Wih + Hc * Ec, g_wih1, bid - PREP_WOUT - 64, tid);
    } else {
#pragma unroll
        for (int j = 0; j < 4; j++) g_f0[tid + j * 256] = 0;
        g_f1[tid] = 0;
    }
}

// ---------------- HMMA fp16 2-term GEMM, 128x128 tile (layer-0 pre-GEMM) ----------------
#define TILE_B 10240
#define STAGE_B (3 * TILE_B)
#define GEMM_SMEM (3 * STAGE_B)

__global__ void __launch_bounds__(256, 2) mma_gemm(
    const __half* __restrict__ Ahi, const __half* __restrict__ Alo,
    const __half* __restrict__ Bh,
    const float* __restrict__ bias, float* __restrict__ C, int Nact)
{
    extern __shared__ __align__(16) char smem[];
    const u32 sb = smem_u32(smem);
    const int tid = threadIdx.x;
    const int wid = tid >> 5, lane = tid & 31;
    const int m0 = blockIdx.y * 128, n0 = blockIdx.x * 128;
    const int wm = (wid >> 2) * 64, wn = (wid & 3) * 32;

    const int row0 = tid >> 2, seg0 = tid & 3;
    const int row1 = (tid + 256) >> 2, seg1 = (tid + 256) & 3;

    float acc[4][4][4];
#pragma unroll
    for (int i = 0; i < 4; i++)
#pragma unroll
        for (int j = 0; j < 4; j++)
#pragma unroll
            for (int q = 0; q < 4; q++) acc[i][j][q] = 0.f;

    auto load_chunk = [&](int k0, int stage) {
        const u32 base = sb + stage * STAGE_B;
#pragma unroll
        for (int h = 0; h < 2; h++) {
            const int row = h ? row1 : row0;
            const int seg = h ? seg1 : seg0;
            const u32 dst = base + row * 80 + seg * 16;
            const size_t aoff = (size_t)(m0 + row) * 256 + k0 + seg * 8;
            cpa16(dst, Ahi + aoff, 16);
            cpa16(dst + TILE_B, Alo + aoff, 16);
            const int br = n0 + row;
            const u32 sz = (br < Nact) ? 16u : 0u;
            const int brc = (br < Nact) ? br : (Nact - 1);
            cpa16(dst + 2 * TILE_B, Bh + (size_t)brc * 256 + k0 + seg * 8, sz);
        }
        cp_commit();
    };

    const u32 arow = (wm + (lane & 15)) * 80 + (lane >> 4) * 16;
    const u32 brow = (wn + (lane & 7) + ((lane >> 4) & 1) * 8) * 80 + ((lane >> 3) & 1) * 16;

    load_chunk(0, 0);
    load_chunk(32, 1);

#pragma unroll 1
    for (int ic = 0; ic < 8; ic++) {
        if (ic < 7) asm volatile("cp.async.wait_group 1;" ::: "memory");
        else        asm volatile("cp.async.wait_group 0;" ::: "memory");
        __syncthreads();
        if (ic < 6) load_chunk((ic + 2) * 32, (ic + 2) % 3);

        const u32 base = sb + (ic % 3) * STAGE_B;
        const u32 aHi = base, aLo = base + TILE_B, bHm = base + 2 * TILE_B;
#pragma unroll
        for (int kk = 0; kk < 2; kk++) {
            u32 af[4][4], bf[2][4];
#pragma unroll
            for (int jb = 0; jb < 2; jb++)
                ldsm_x4(bf[jb], bHm + brow + jb * 16 * 80 + kk * 32);
#pragma unroll
            for (int im = 0; im < 4; im++)
                ldsm_x4(af[im], aHi + arow + im * 16 * 80 + kk * 32);
#pragma unroll
            for (int im = 0; im < 4; im++)
#pragma unroll
                for (int jn = 0; jn < 4; jn++)
                    mma_f16(acc[im][jn], af[im], &bf[jn >> 1][(jn & 1) * 2]);
#pragma unroll
            for (int im = 0; im < 4; im++)
                ldsm_x4(af[im], aLo + arow + im * 16 * 80 + kk * 32);
#pragma unroll
            for (int im = 0; im < 4; im++)
#pragma unroll
                for (int jn = 0; jn < 4; jn++)
                    mma_f16(acc[im][jn], af[im], &bf[jn >> 1][(jn & 1) * 2]);
        }
    }

    const int rbase = m0 + wm + (lane >> 2);
    const int cbase = n0 + wn + (lane & 3) * 2;
#pragma unroll
    for (int im = 0; im < 4; im++) {
#pragma unroll
        for (int jn = 0; jn < 4; jn++) {
            int n = cbase + jn * 8;
            if (n < Nact) {
                float bx = bias[n], by = bias[n + 1];
                int r0 = rbase + im * 16;
                *reinterpret_cast<float2*>(C + (size_t)r0 * Nact + n) =
                    make_float2(acc[im][jn][0] + bx, acc[im][jn][1] + by);
                *reinterpret_cast<float2*>(C + (size_t)(r0 + 8) * Nact + n) =
                    make_float2(acc[im][jn][2] + bx, acc[im][jn][3] + by);
            }
        }
    }
}

// ---------------- HMMA fp16 1-term GEMM, 128x128 tile (output projection) ----------------
#define STAGE1_B (2 * TILE_B)            // A | B
#define GEMM1_SMEM (3 * STAGE1_B)        // 61440

__global__ void __launch_bounds__(256, 2) mma_gemm_1t(
    const __half* __restrict__ Ah, const __half* __restrict__ Bh,
    const float* __restrict__ bias, float* __restrict__ C, int Nact)
{
    extern __shared__ __align__(16) char smem[];
    const u32 sb = smem_u32(smem);
    const int tid = threadIdx.x;
    const int wid = tid >> 5, lane = tid & 31;
    const int m0 = blockIdx.y * 128, n0 = blockIdx.x * 128;
    const int wm = (wid >> 2) * 64, wn = (wid & 3) * 32;

    const int row0 = tid >> 2, seg0 = tid & 3;
    const int row1 = (tid + 256) >> 2, seg1 = (tid + 256) & 3;

    float acc[4][4][4];
#pragma unroll
    for (int i = 0; i < 4; i++)
#pragma unroll
        for (int j = 0; j < 4; j++)
#pragma unroll
            for (int q = 0; q < 4; q++) acc[i][j][q] = 0.f;

    auto load_chunk = [&](int k0, int stage) {
        const u32 base = sb + stage * STAGE1_B;
#pragma unroll
        for (int h = 0; h < 2; h++) {
            const int row = h ? row1 : row0;
            const int seg = h ? seg1 : seg0;
            const u32 dst = base + row * 80 + seg * 16;
            cpa16(dst, Ah + (size_t)(m0 + row) * 256 + k0 + seg * 8, 16);
            const int br = n0 + row;
            const u32 sz = (br < Nact) ? 16u : 0u;
            const int brc = (br < Nact) ? br : (Nact - 1);
            cpa16(dst + TILE_B, Bh + (size_t)brc * 256 + k0 + seg * 8, sz);
        }
        cp_commit();
    };

    const u32 arow = (wm + (lane & 15)) * 80 + (lane >> 4) * 16;
    const u32 brow = (wn + (lane & 7) + ((lane >> 4) & 1) * 8) * 80 + ((lane >> 3) & 1) * 16;

    load_chunk(0, 0);
    load_chunk(32, 1);

#pragma unroll 1
    for (int ic = 0; ic < 8; ic++) {
        if (ic < 7) asm volatile("cp.async.wait_group 1;" ::: "memory");
        else        asm volatile("cp.async.wait_group 0;" ::: "memory");
        __syncthreads();
        if (ic < 6) load_chunk((ic + 2) * 32, (ic + 2) % 3);

        const u32 base = sb + (ic % 3) * STAGE1_B;
        const u32 aHi = base, bHm = base + TILE_B;
#pragma unroll
        for (int kk = 0; kk < 2; kk++) {
            u32 af[4][4], bf[2][4];
#pragma unroll
            for (int jb = 0; jb < 2; jb++)
                ldsm_x4(bf[jb], bHm + brow + jb * 16 * 80 + kk * 32);
#pragma unroll
            for (int im = 0; im < 4; im++)
                ldsm_x4(af[im], aHi + arow + im * 16 * 80 + kk * 32);
#pragma unroll
            for (int im = 0; im < 4; im++)
#pragma unroll
                for (int jn = 0; jn < 4; jn++)
                    mma_f16(acc[im][jn], af[im], &bf[jn >> 1][(jn & 1) * 2]);
        }
    }

    const int rbase = m0 + wm + (lane >> 2);
    const int cbase = n0 + wn + (lane & 3) * 2;
#pragma unroll
    for (int im = 0; im < 4; im++) {
#pragma unroll
        for (int jn = 0; jn < 4; jn++) {
            int n = cbase + jn * 8;
            if (n < Nact) {
                float bx = bias[n], by = bias[n + 1];
                int r0 = rbase + im * 16;
                *reinterpret_cast<float2*>(C + (size_t)r0 * Nact + n) =
                    make_float2(acc[im][jn][0] + bx, acc[im][jn][1] + by);
                *reinterpret_cast<float2*>(C + (size_t)(r0 + 8) * Nact + n) =
                    make_float2(acc[im][jn][2] + bx, acc[im][jn][3] + by);
            }
        }
    }
}

// ---------------- fused wavefront pipeline: scan0 | gemm1 | scan1 (R14 winner) ----------------
#define FSC_W4 16
#define FUSED_SMEM (FSC_W4 * 256 * 16 + 2 * 256 * 4)

__global__ void __launch_bounds__(256, 1) fused_pipeline(
    const float* __restrict__ pre0, float* __restrict__ pre1,
    const float* __restrict__ Whh, const float* __restrict__ bhh,
    const __half* __restrict__ wih1, const float* __restrict__ bih1,
    __half* __restrict__ ahi, __half* __restrict__ alo,
    __half* __restrict__ bhi, __half* __restrict__ blo,
    float* __restrict__ hlast)
{
    extern __shared__ __align__(16) float sm[];
    const int role = blockIdx.x;
    const int tid = threadIdx.x;

    if (role < 128) {
        const int layer = role >> 6;
        const int b = role & 63;
        const int r = tid;
        float4* w4 = reinterpret_cast<float4*>(sm);
        float* hbuf = sm + FSC_W4 * 256 * 4;
        const float* W = Whh + (size_t)layer * Hc * Hc;

#pragma unroll
        for (int k4 = 0; k4 < FSC_W4; k4++)
            w4[k4 * 256 + r] = *reinterpret_cast<const float4*>(&W[r * 256 + k4 * 4]);
        u64 wreg[96];
#pragma unroll
        for (int j = 0; j < 48; j++) {
            ulonglong2 v = *reinterpret_cast<const ulonglong2*>(&W[r * 256 + 64 + j * 4]);
            wreg[2 * j] = v.x; wreg[2 * j + 1] = v.y;
        }
        const float bias = bhh[layer * Hc + r];
        hbuf[r] = 0.f;
        __syncthreads();

        const float* preb = (layer ? pre1 : pre0) + (size_t)b * Tc * Hc;
        __half* ohi = (layer ? bhi : ahi) + (size_t)b * Tc * Hc;
        __half* olo = (layer ? blo : alo) + (size_t)b * Tc * Hc;
        const ulonglong2* w2s = reinterpret_cast<const ulonglong2*>(sm);

        float hn = 0.f;
#pragma unroll 1
        for (int c = 0; c < NCH; c++) {
            if (layer) {
                if (tid == 0) {
                    while (atomicAdd(&g_f1[(b >> 2) * NCH + c], 0) == 0) __nanosleep(200);
                }
                __syncthreads();
                __threadfence();
            }
            float pc = preb[(c * CST) * Hc + r];
#pragma unroll 1
            for (int tt = 0; tt < CST; tt++) {
                const int t = c * CST + tt;
                float pn = (tt < CST - 1) ? preb[(t + 1) * Hc + r] : 0.f;
                const ulonglong2* hc = reinterpret_cast<const ulonglong2*>(hbuf + (t & 1) * 256);
                u64 a0 = pk2(pc + bias, 0.f), a1 = 0ull, a2 = 0ull, a3 = 0ull;
#pragma unroll
                for (int k4 = 0; k4 < FSC_W4; k4++) {
                    ulonglong2 w = w2s[k4 * 256 + r];
                    ulonglong2 h = hc[k4];
                    a0 = fma2(w.x, h.x, a0);
                    a0 = fma2(w.y, h.y, a0);
                }
#pragma unroll
                for (int j = 0; j < 16; j++) {
                    ulonglong2 h = hc[FSC_W4 + j];
                    a1 = fma2(wreg[2 * j], h.x, a1);
                    a1 = fma2(wreg[2 * j + 1], h.y, a1);
                }
#pragma unroll
                for (int j = 16; j < 32; j++) {
                    ulonglong2 h = hc[FSC_W4 + j];
                    a2 = fma2(wreg[2 * j], h.x, a2);
                    a2 = fma2(wreg[2 * j + 1], h.y, a2);
                }
#pragma unroll
                for (int j = 32; j < 48; j++) {
                    ulonglong2 h = hc[FSC_W4 + j];
                    a3 = fma2(wreg[2 * j], h.x, a3);
                    a3 = fma2(wreg[2 * j + 1], h.y, a3);
                }
                float2 p0 = up2(a0), p1 = up2(a1), p2 = up2(a2), p3 = up2(a3);
                hn = tanh_acc(((p0.x + p0.y) + (p1.x + p1.y)) + ((p2.x + p2.y) + (p3.x + p3.y)));
                __half hh = __float2half_rn(hn);
                __half hl = __float2half_rn(hn - __half2float(hh));
                ohi[t * Hc + r] = hh;
                olo[t * Hc + r] = hl;
                hbuf[((t + 1) & 1) * 256 + r] = hn;
                __syncthreads();
                pc = pn;
            }
            if (!layer) {
                __threadfence();
                __syncthreads();
                if (tid == 0) atomicExch(&g_f0[b * NCH + c], 1);
            }
        }
        hlast[layer * Bc * Hc + b * Hc + r] = hn;
    } else {
        const int g = role - 128;
        const u32 sb = smem_u32(sm);
        const int wid = tid >> 5, lane = tid & 31;
        const int wm = (wid >> 2) * 64, wn = (wid & 3) * 32;
        const int row0 = tid >> 2, seg0 = tid & 3;
        const int row1 = (tid + 256) >> 2, seg1 = (tid + 256) & 3;
        const u32 arow = (wm + (lane & 15)) * 80 + (lane >> 4) * 16;
        const u32 brow = (wn + (lane & 7) + ((lane >> 4) & 1) * 8) * 80 + ((lane >> 3) & 1) * 16;

#pragma unroll 1
        for (int c = 0; c < NCH; c++) {
            if (tid == 0) {
#pragma unroll 1
                for (int i = 0; i < 4; i++)
                    while (atomicAdd(&g_f0[(4 * g + i) * NCH + c], 0) == 0) __nanosleep(100);
            }
            __syncthreads();
            __threadfence();

#pragma unroll 1
            for (int nt = 0; nt < 2; nt++) {
                float acc[4][4][4];
#pragma unroll
                for (int i = 0; i < 4; i++)
#pragma unroll
                    for (int j = 0; j < 4; j++)
#pragma unroll
                        for (int q = 0; q < 4; q++) acc[i][j][q] = 0.f;

#pragma unroll 1
                for (int kc = 0; kc < 8; kc++) {
#pragma unroll
                    for (int h = 0; h < 2; h++) {
                        const int row = h ? row1 : row0;
                        const int seg = h ? seg1 : seg0;
                        const int bb = 4 * g + (row >> 5);
                        const int t = c * CST + (row & 31);
                        const size_t aoff = ((size_t)(bb * 512 + t)) * 256 + kc * 32 + seg * 8;
                        const u32 dst = sb + row * 80 + seg * 16;
                        cpa16(dst, ahi + aoff, 16);
                        cpa16(dst + TILE_B, alo + aoff, 16);
                        const size_t boff = (size_t)(nt * 128 + row) * 256 + kc * 32 + seg * 8;
                        cpa16(dst + 2 * TILE_B, wih1 + boff, 16);
                    }
                    cp_commit();
                    asm volatile("cp.async.wait_group 0;" ::: "memory");
                    __syncthreads();

                    const u32 aHi = sb, aLo = sb + TILE_B, bHm = sb + 2 * TILE_B;
#pragma unroll
                    for (int kk = 0; kk < 2; kk++) {
                        u32 af[4][4], bf[2][4];
#pragma unroll
                        for (int jb = 0; jb < 2; jb++)
                            ldsm_x4(bf[jb], bHm + brow + jb * 16 * 80 + kk * 32);
#pragma unroll
                        for (int im = 0; im < 4; im++)
                            ldsm_x4(af[im], aHi + arow + im * 16 * 80 + kk * 32);
#pragma unroll
                        for (int im = 0; im < 4; im++)
#pragma unroll
                            for (int jn = 0; jn < 4; jn++)
                                mma_f16(acc[im][jn], af[im], &bf[jn >> 1][(jn & 1) * 2]);
#pragma unroll
                        for (int im = 0; im < 4; im++)
                            ldsm_x4(af[im], aLo + arow + im * 16 * 80 + kk * 32);
#pragma unroll
                        for (int im = 0; im < 4; im++)
#pragma unroll
                            for (int jn = 0; jn < 4; jn++)
                                mma_f16(acc[im][jn], af[im], &bf[jn >> 1][(jn & 1) * 2]);
                    }
                    __syncthreads();
                }
#pragma unroll
                for (int im = 0; im < 4; im++) {
#pragma unroll
                    for (int jn = 0; jn < 4; jn++) {
                        const int n = nt * 128 + wn + (lane & 3) * 2 + jn * 8;
                        const float bx = bih1[n], by = bih1[n + 1];
                        const int rl0 = wm + (lane >> 2) + im * 16;
                        const int b0 = 4 * g + (rl0 >> 5), t0 = c * CST + (rl0 & 31);
                        *reinterpret_cast<float2*>(pre1 + ((size_t)(b0 * 512 + t0)) * 256 + n) =
                            make_float2(acc[im][jn][0] + bx, acc[im][jn][1] + by);
                        const int rl1 = rl0 + 8;
                        const int b1 = 4 * g + (rl1 >> 5), t1 = c * CST + (rl1 & 31);
                        *reinterpret_cast<float2*>(pre1 + ((size_t)(b1 * 512 + t1)) * 256 + n) =
                            make_float2(acc[im][jn][2] + bx, acc[im][jn][3] + by);
                    }
                }
            }
            __threadfence();
            __syncthreads();
            if (tid == 0) atomicExch(&g_f1[g * NCH + c], 1);
        }
    }
}

__global__ void tail_kernel(const int* __restrict__ x, float* __restrict__ outSeq) {
    int i = threadIdx.x;
    outSeq[i] = (float)x[i * T2c + (T2c - 1)];
}

extern "C" void kernel_launch(void* const* d_in, const int* in_sizes, int n_in,
                              void* d_out, int out_size) {
    const int*   x    = (const int*)d_in[0];
    const float* tab  = (const float*)d_in[1];
    const float* Wih  = (const float*)d_in[2];
    const float* Whh  = (const float*)d_in[3];
    const float* bih  = (const float*)d_in[4];
    const float* bhh  = (const float*)d_in[5];
    const float* Wout = (const float*)d_in[6];
    const float* bout = (const float*)d_in[7];
    float* out = (float*)d_out;

    float *pre0, *pre1;
    __half *ahi, *alo, *bhi, *blo, *whi, *wih0, *wih1;
    cudaGetSymbolAddress((void**)&pre0, g_pre0);
    cudaGetSymbolAddress((void**)&pre1, g_pre1);
    cudaGetSymbolAddress((void**)&ahi, g_ahi);
    cudaGetSymbolAddress((void**)&alo, g_alo);
    cudaGetSymbolAddress((void**)&bhi, g_bhi);
    cudaGetSymbolAddress((void**)&blo, g_blo);
    cudaGetSymbolAddress((void**)&whi, g_whi);
    cudaGetSymbolAddress((void**)&wih0, g_wih0);
    cudaGetSymbolAddress((void**)&wih1, g_wih1);

    cudaFuncSetAttribute(mma_gemm, cudaFuncAttributeMaxDynamicSharedMemorySize, GEMM_SMEM);
    cudaFuncSetAttribute(mma_gemm_1t, cudaFuncAttributeMaxDynamicSharedMemorySize, GEMM1_SMEM);
    cudaFuncSetAttribute(fused_pipeline, cudaFuncAttributeMaxDynamicSharedMemorySize, FUSED_SMEM);

    const size_t LOGITS = (size_t)Bc * Tc * Vc;
    float* lstate = out + LOGITS;
    float* seq = out + LOGITS + 2 * Bc * Hc;

    // prologue: embed + one-shot weight conversions/flag reset
    embed_kernel<<<(Bc * Tc) / 4, 256>>>(x, tab, ahi, alo);
    prep_kernel<<<PREP_BLOCKS, 256>>>(Wih, Wout);

    // layer-0 pre-GEMM (2-term, feeds the recurrence)
    mma_gemm<<<dim3(2, 256), dim3(256), GEMM_SMEM>>>(ahi, alo, wih0, bih, pre0, Hc);

    // fused wavefront: scan0 | gemm1 | scan1
    fused_pipeline<<<144, 256, FUSED_SMEM>>>(pre0, pre1, Whh, bhh, wih1, bih + Hc,
                                             ahi, alo, bhi, blo, lstate);

    // output projection: 1-term fp16, 128x128, 2 CTA/SM
    mma_gemm_1t<<<dim3((Vc + 127) / 128, 256), dim3(256), GEMM1_SMEM>>>(bhi, whi, bout, out, Vc);

    tail_kernel<<<1, Bc>>>(x, seq);
}